// round 2
// baseline (speedup 1.0000x reference)
#include <cuda_runtime.h>
#include <math.h>

// Problem constants
#define TT   8192      // tokens = 4*2048
#define DD   2048      // model dim
#define NE   8         // experts
#define BB   512       // bottleneck dim
#define NBK  16        // buckets = expert*2 + k

// GEMM tile
#define BM   128
#define BNT  128
#define BKT  16
#define LDSS 132       // padded stride (keeps 16B alignment, reduces conflicts)

// Scratch (static device globals — allocation-free)
__device__ int   g_cnt[NBK];
__device__ int   g_tok[NBK][TT];
__device__ float g_twt[NBK][TT];
__device__ int   g_sel[TT][2];
__device__ float g_wgt[TT][2];
__device__ float g_h[2][TT][BB];    // routed bottleneck activations, token-indexed
__device__ float g_hs[TT][BB];      // shared-expert bottleneck activations

__device__ __forceinline__ float gelu_f(float v) {
    return 0.5f * v * (1.0f + erff(v * 0.70710678118654752f));
}

__global__ void k_reset() {
    if (threadIdx.x < NBK) g_cnt[threadIdx.x] = 0;
}

// One warp per token: gate logits -> softmax -> top2 -> renormalize -> bucket
__global__ void k_route(const float* __restrict__ x, const float* __restrict__ gw) {
    int t    = blockIdx.x * 8 + (threadIdx.x >> 5);
    int lane = threadIdx.x & 31;
    if (t >= TT) return;

    const float4* xr = (const float4*)(x + (size_t)t * DD);
    float acc[NE];
#pragma unroll
    for (int e = 0; e < NE; e++) acc[e] = 0.f;

    for (int i = lane; i < DD / 4; i += 32) {
        float4 xv = xr[i];
#pragma unroll
        for (int e = 0; e < NE; e++) {
            float4 gv = ((const float4*)(gw + (size_t)e * DD))[i];
            acc[e] += xv.x * gv.x + xv.y * gv.y + xv.z * gv.z + xv.w * gv.w;
        }
    }
#pragma unroll
    for (int e = 0; e < NE; e++) {
#pragma unroll
        for (int o = 16; o > 0; o >>= 1)
            acc[e] += __shfl_down_sync(0xffffffffu, acc[e], o);
    }

    if (lane == 0) {
        float mx = acc[0];
#pragma unroll
        for (int e = 1; e < NE; e++) mx = fmaxf(mx, acc[e]);
        float p[NE];
#pragma unroll
        for (int e = 0; e < NE; e++) p[e] = expf(acc[e] - mx);
        // top-2 (ties -> lower index, matching lax.top_k)
        int i1 = 0;
#pragma unroll
        for (int e = 1; e < NE; e++) if (p[e] > p[i1]) i1 = e;
        int i2 = (i1 == 0) ? 1 : 0;
#pragma unroll
        for (int e = 0; e < NE; e++) {
            if (e == i1) continue;
            if (p[e] > p[i2]) i2 = e;
        }
        float w1 = p[i1], w2 = p[i2];
        float inv = 1.0f / (w1 + w2);
        w1 *= inv; w2 *= inv;

        g_sel[t][0] = i1; g_sel[t][1] = i2;
        g_wgt[t][0] = w1; g_wgt[t][1] = w2;

        int b0 = i1 * 2 + 0;
        int s0 = atomicAdd(&g_cnt[b0], 1);
        g_tok[b0][s0] = t; g_twt[b0][s0] = w1;
        int b1 = i2 * 2 + 1;
        int s1 = atomicAdd(&g_cnt[b1], 1);
        g_tok[b1][s1] = t; g_twt[b1][s1] = w2;
    }
}

enum { DOWN_S = 0, DOWN_R = 1, UP_S = 2, UP_R = 3 };

// NT fp32 GEMM, 128x128x16 tile, 256 threads, 8x8 per-thread microtile.
// A rows optionally gathered through per-bucket token lists.
template <int MODE>
__global__ __launch_bounds__(256, 2) void k_gemm(
    const float* __restrict__ x,      // A source (x or ignored for g_* modes)
    const float* __restrict__ W,      // B matrix base
    const float* __restrict__ bias,   // bd / bs_d / bs_u
    const float* __restrict__ bu,     // only UP_S
    float* __restrict__ out,          // only UP_S / UP_R
    int kk)                           // only UP_R
{
    __shared__ float As[BKT][LDSS];
    __shared__ float Bs[BKT][LDSS];

    const int tid = threadIdx.x;
    const int m0 = blockIdx.x * BM;
    const int n0 = blockIdx.y * BNT;

    int M = TT;
    const int Kd = (MODE == DOWN_S || MODE == DOWN_R) ? DD : BB;
    const int* tok = nullptr;
    const float* twt = nullptr;
    int eidx = 0, kidx = 0;

    if (MODE == DOWN_R || MODE == UP_R) {
        int bucket = (MODE == DOWN_R) ? (int)blockIdx.z : ((int)blockIdx.z * 2 + kk);
        M = g_cnt[bucket];
        if (m0 >= M) return;
        eidx = bucket >> 1;
        kidx = bucket & 1;
        tok = g_tok[bucket];
        twt = g_twt[bucket];
    }

    const float* A; int lda;
    const float* Bm; int ldb;
    if (MODE == DOWN_S)      { A = x;             lda = DD; Bm = W;                               ldb = DD; }
    else if (MODE == DOWN_R) { A = x;             lda = DD; Bm = W + (size_t)eidx * BB * DD;      ldb = DD; }
    else if (MODE == UP_S)   { A = &g_hs[0][0];   lda = BB; Bm = W;                               ldb = BB; }
    else                     { A = &g_h[kk][0][0];lda = BB; Bm = W + (size_t)eidx * DD * BB;      ldb = BB; }

    // Resolve this thread's two A-tile rows once (fixed across K loop)
    int arow[2];
#pragma unroll
    for (int i = 0; i < 2; i++) {
        int p = tid + i * 256;
        int r = m0 + (p >> 2);
        if (MODE == DOWN_R || MODE == UP_R) arow[i] = (r < M) ? tok[r] : -1;
        else                                arow[i] = r;
    }

    float acc[8][8];
#pragma unroll
    for (int i = 0; i < 8; i++)
#pragma unroll
        for (int j = 0; j < 8; j++) acc[i][j] = 0.f;

    const int tx = tid & 15;
    const int ty = tid >> 4;

    for (int kt = 0; kt < Kd; kt += BKT) {
#pragma unroll
        for (int i = 0; i < 2; i++) {
            int p = tid + i * 256;
            int row = p >> 2, c4 = (p & 3) * 4;
            float4 v = make_float4(0.f, 0.f, 0.f, 0.f);
            if (arow[i] >= 0)
                v = *(const float4*)(A + (size_t)arow[i] * lda + kt + c4);
            As[c4 + 0][row] = v.x; As[c4 + 1][row] = v.y;
            As[c4 + 2][row] = v.z; As[c4 + 3][row] = v.w;
        }
#pragma unroll
        for (int i = 0; i < 2; i++) {
            int p = tid + i * 256;
            int row = p >> 2, c4 = (p & 3) * 4;
            float4 v = *(const float4*)(Bm + (size_t)(n0 + row) * ldb + kt + c4);
            Bs[c4 + 0][row] = v.x; Bs[c4 + 1][row] = v.y;
            Bs[c4 + 2][row] = v.z; Bs[c4 + 3][row] = v.w;
        }
        __syncthreads();

#pragma unroll
        for (int q = 0; q < BKT; q++) {
            float ra[8], rb[8];
            *(float4*)&ra[0] = *(const float4*)&As[q][ty * 8];
            *(float4*)&ra[4] = *(const float4*)&As[q][ty * 8 + 4];
            *(float4*)&rb[0] = *(const float4*)&Bs[q][tx * 8];
            *(float4*)&rb[4] = *(const float4*)&Bs[q][tx * 8 + 4];
#pragma unroll
            for (int i = 0; i < 8; i++)
#pragma unroll
                for (int j = 0; j < 8; j++)
                    acc[i][j] = fmaf(ra[i], rb[j], acc[i][j]);
        }
        __syncthreads();
    }

    // Epilogue
#pragma unroll
    for (int i = 0; i < 8; i++) {
        int r = m0 + ty * 8 + i;
        if ((MODE == DOWN_R || MODE == UP_R) && r >= M) continue;
        int t = (MODE == DOWN_R || MODE == UP_R) ? tok[r] : r;
#pragma unroll
        for (int j = 0; j < 8; j++) {
            int n = n0 + tx * 8 + j;
            if (MODE == DOWN_S) {
                g_hs[t][n] = gelu_f(acc[i][j] + bias[n]);
            } else if (MODE == DOWN_R) {
                float v = gelu_f(acc[i][j] + bias[(size_t)eidx * BB + n]) * twt[r];
                g_h[kidx][t][n] = v;
            } else if (MODE == UP_S) {
                float v = acc[i][j] + bias[n];
                v += g_wgt[t][0] * bu[(size_t)g_sel[t][0] * DD + n];
                v += g_wgt[t][1] * bu[(size_t)g_sel[t][1] * DD + n];
                out[(size_t)t * DD + n] = v;
            } else { // UP_R: race-free within a launch (one slot per token per k)
                out[(size_t)t * DD + n] += acc[i][j];
            }
        }
    }
}

extern "C" void kernel_launch(void* const* d_in, const int* in_sizes, int n_in,
                              void* d_out, int out_size) {
    const float* x   = (const float*)d_in[0];
    const float* gw  = (const float*)d_in[1];
    const float* wd  = (const float*)d_in[2];
    const float* bd  = (const float*)d_in[3];
    const float* wu  = (const float*)d_in[4];
    const float* bu  = (const float*)d_in[5];
    const float* wsd = (const float*)d_in[6];
    const float* bsd = (const float*)d_in[7];
    const float* wsu = (const float*)d_in[8];
    const float* bsu = (const float*)d_in[9];
    float* out = (float*)d_out;

    k_reset<<<1, 32>>>();
    k_route<<<TT / 8, 256>>>(x, gw);

    dim3 gds(TT / BM, BB / BNT);            // 64 x 4
    k_gemm<DOWN_S><<<gds, 256>>>(x, wsd, bsd, nullptr, nullptr, 0);

    dim3 gdr(TT / BM, BB / BNT, NBK);       // 64 x 4 x 16 (early-exit past count)
    k_gemm<DOWN_R><<<gdr, 256>>>(x, wd, bd, nullptr, nullptr, 0);

    dim3 gus(TT / BM, DD / BNT);            // 64 x 16 — writes every out element
    k_gemm<UP_S><<<gus, 256>>>(x, wsu, bsu, bu, out, 0);

    dim3 gur(TT / BM, DD / BNT, NE);        // 64 x 16 x 8, per k-phase
    k_gemm<UP_R><<<gur, 256>>>(x, wu, nullptr, nullptr, out, 0);
    k_gemm<UP_R><<<gur, 256>>>(x, wu, nullptr, nullptr, out, 1);
}

// round 4
// speedup vs baseline: 2.0989x; 2.0989x over previous
#include <cuda_runtime.h>
#include <cuda_fp16.h>
#include <math.h>
#include <stdint.h>

#define TT   8192
#define DD   2048
#define NE   8
#define BB   512
#define NBK  16

#define BM   128
#define BN   128
#define BK   32
#define LDA  40                    // halves per smem row (64B data + 16B pad)
#define TILE_H  (BM * LDA * 2)     // 10240 B per matrix (A_h/A_l/B_h/B_l)
#define STAGE_B (4 * TILE_H)       // 40960 B per stage
#define DSMEM   (2 * STAGE_B)      // 81920 B

// Scratch (static device globals — allocation-free)
__device__ int   g_cnt[NBK];
__device__ int   g_tok[NBK][TT];
__device__ float g_twt[NBK][TT];
__device__ int   g_sel[TT][2];
__device__ float g_wgt[TT][2];
__device__ float g_h[2][TT][BB];
__device__ float g_hs[TT][BB];

__device__ __forceinline__ uint32_t smem_u32(const void* p) {
    uint32_t a;
    asm("{ .reg .u64 t; cvta.to.shared.u64 t, %1; cvt.u32.u64 %0, t; }" : "=r"(a) : "l"(p));
    return a;
}
__device__ __forceinline__ void ldsm4(uint32_t* r, uint32_t a) {
    asm volatile("ldmatrix.sync.aligned.m8n8.x4.shared.b16 {%0,%1,%2,%3}, [%4];"
                 : "=r"(r[0]), "=r"(r[1]), "=r"(r[2]), "=r"(r[3]) : "r"(a));
}
__device__ __forceinline__ void ldsm2(uint32_t* r, uint32_t a) {
    asm volatile("ldmatrix.sync.aligned.m8n8.x2.shared.b16 {%0,%1}, [%2];"
                 : "=r"(r[0]), "=r"(r[1]) : "r"(a));
}
__device__ __forceinline__ void mma16816(float* c, const uint32_t* a, const uint32_t* b) {
    asm volatile("mma.sync.aligned.m16n8k16.row.col.f32.f16.f16.f32 "
                 "{%0,%1,%2,%3}, {%4,%5,%6,%7}, {%8,%9}, {%0,%1,%2,%3};"
                 : "+f"(c[0]), "+f"(c[1]), "+f"(c[2]), "+f"(c[3])
                 : "r"(a[0]), "r"(a[1]), "r"(a[2]), "r"(a[3]), "r"(b[0]), "r"(b[1]));
}
__device__ __forceinline__ uint32_t packh(half a, half b) {
    __half2 h = __halves2half2(a, b);
    return *(uint32_t*)&h;
}
__device__ __forceinline__ float gelu_f(float v) {
    return 0.5f * v * (1.0f + erff(v * 0.70710678118654752f));
}

// ---------------- routing ----------------
__global__ void k_reset() {
    if (threadIdx.x < NBK) g_cnt[threadIdx.x] = 0;
}

__global__ void k_route(const float* __restrict__ x, const float* __restrict__ gw) {
    int t    = blockIdx.x * 8 + (threadIdx.x >> 5);
    int lane = threadIdx.x & 31;
    if (t >= TT) return;
    const float4* xr = (const float4*)(x + (size_t)t * DD);
    float acc[NE];
#pragma unroll
    for (int e = 0; e < NE; e++) acc[e] = 0.f;
    for (int i = lane; i < DD / 4; i += 32) {
        float4 xv = xr[i];
#pragma unroll
        for (int e = 0; e < NE; e++) {
            float4 gv = ((const float4*)(gw + (size_t)e * DD))[i];
            acc[e] += xv.x * gv.x + xv.y * gv.y + xv.z * gv.z + xv.w * gv.w;
        }
    }
#pragma unroll
    for (int e = 0; e < NE; e++)
#pragma unroll
        for (int o = 16; o > 0; o >>= 1)
            acc[e] += __shfl_down_sync(0xffffffffu, acc[e], o);
    if (lane == 0) {
        float mx = acc[0];
#pragma unroll
        for (int e = 1; e < NE; e++) mx = fmaxf(mx, acc[e]);
        float p[NE];
#pragma unroll
        for (int e = 0; e < NE; e++) p[e] = expf(acc[e] - mx);
        int i1 = 0;
#pragma unroll
        for (int e = 1; e < NE; e++) if (p[e] > p[i1]) i1 = e;
        int i2 = (i1 == 0) ? 1 : 0;
#pragma unroll
        for (int e = 0; e < NE; e++) { if (e != i1 && p[e] > p[i2]) i2 = e; }
        float w1 = p[i1], w2 = p[i2];
        float inv = 1.0f / (w1 + w2);
        w1 *= inv; w2 *= inv;
        g_sel[t][0] = i1; g_sel[t][1] = i2;
        g_wgt[t][0] = w1; g_wgt[t][1] = w2;
        int b0 = i1 * 2 + 0;
        int s0 = atomicAdd(&g_cnt[b0], 1);
        g_tok[b0][s0] = t; g_twt[b0][s0] = w1;
        int b1 = i2 * 2 + 1;
        int s1 = atomicAdd(&g_cnt[b1], 1);
        g_tok[b1][s1] = t; g_twt[b1][s1] = w2;
    }
}

// ---------------- mma.sync 3xFP16 GEMM ----------------
enum { DOWN_S = 0, DOWN_R = 1, UP_S = 2, UP_R = 3 };

template <int MODE>
__global__ __launch_bounds__(256) void k_mma(
    const float* __restrict__ x, const float* __restrict__ W,
    const float* __restrict__ bias, const float* __restrict__ bu,
    float* __restrict__ out, int kk)
{
    extern __shared__ char dyn[];
    __shared__ int   s_row[BM];
    __shared__ float s_wt[BM];

    const int tid = threadIdx.x, wid = tid >> 5, lane = tid & 31;
    const int m0 = blockIdx.x * BM, n0 = blockIdx.y * BN;

    int M = TT, eidx = 0, kidx = 0;
    const int* tok = nullptr;
    const float* twt = nullptr;
    if (MODE == DOWN_R || MODE == UP_R) {
        int bucket = (MODE == DOWN_R) ? (int)blockIdx.z : ((int)blockIdx.z * 2 + kk);
        M = g_cnt[bucket];
        if (m0 >= M) return;
        eidx = bucket >> 1;
        kidx = bucket & 1;
        tok = g_tok[bucket];
        twt = g_twt[bucket];
    }

    const float* A; int lda;
    const float* Bm; int ldb; int Kd;
    if (MODE == DOWN_S)      { A = x;              lda = DD; Bm = W;                          ldb = DD; Kd = DD; }
    else if (MODE == DOWN_R) { A = x;              lda = DD; Bm = W + (size_t)eidx * BB * DD; ldb = DD; Kd = DD; }
    else if (MODE == UP_S)   { A = &g_hs[0][0];    lda = BB; Bm = W;                          ldb = BB; Kd = BB; }
    else                     { A = &g_h[kk][0][0]; lda = BB; Bm = W + (size_t)eidx * DD * BB; ldb = BB; Kd = BB; }

    if (tid < BM) {
        int r = m0 + tid;
        if (MODE == DOWN_R || MODE == UP_R) {
            s_row[tid] = (r < M) ? tok[r] : -1;
            s_wt[tid]  = (r < M) ? twt[r] : 0.f;
        } else {
            s_row[tid] = r;
        }
    }
    __syncthreads();

    const uint32_t sb0 = smem_u32(dyn);
    const int warp_m = wid >> 2, warp_n = wid & 3;   // 2 x 4 warps, 64x32 tile

    float c[4][4][4];
#pragma unroll
    for (int i = 0; i < 4; i++)
#pragma unroll
        for (int j = 0; j < 4; j++)
#pragma unroll
            for (int q = 0; q < 4; q++) c[i][j][q] = 0.f;

    float4 rg[8];
    const int nch = Kd / BK;

    // prologue: chunk 0 -> regs -> smem
    {
        int kt = 0;
#pragma unroll
        for (int it = 0; it < 8; it++) {
            int id = tid + it * 256;
            int row = id >> 3, c4 = id & 7;
            if (it < 4) {
                int tr = s_row[row];
                rg[it] = (tr >= 0) ? *(const float4*)(A + (size_t)tr * lda + kt + c4 * 4)
                                   : make_float4(0.f, 0.f, 0.f, 0.f);
            } else {
                rg[it] = *(const float4*)(Bm + (size_t)(n0 + row - BM) * ldb + kt + c4 * 4);
            }
        }
        char* base = dyn;
#pragma unroll
        for (int it = 0; it < 8; it++) {
            int id = tid + it * 256;
            int row = (it < 4) ? (id >> 3) : ((id >> 3) - BM);
            int c4 = id & 7;
            float4 v = rg[it];
            half hx = __float2half_rn(v.x), hy = __float2half_rn(v.y);
            half hz = __float2half_rn(v.z), hw = __float2half_rn(v.w);
            half lx = __float2half_rn(v.x - __half2float(hx));
            half ly = __float2half_rn(v.y - __half2float(hy));
            half lz = __float2half_rn(v.z - __half2float(hz));
            half lw = __float2half_rn(v.w - __half2float(hw));
            char* h = base + ((it < 4) ? 0 : 2 * TILE_H) + (row * LDA + c4 * 4) * 2;
            *(uint2*)h = make_uint2(packh(hx, hy), packh(hz, hw));
            *(uint2*)(h + TILE_H) = make_uint2(packh(lx, ly), packh(lz, lw));
        }
    }
    __syncthreads();

    for (int ch = 0; ch < nch; ch++) {
        // prefetch next chunk into regs
        if (ch + 1 < nch) {
            int kt = (ch + 1) * BK;
#pragma unroll
            for (int it = 0; it < 8; it++) {
                int id = tid + it * 256;
                int row = id >> 3, c4 = id & 7;
                if (it < 4) {
                    int tr = s_row[row];
                    rg[it] = (tr >= 0) ? *(const float4*)(A + (size_t)tr * lda + kt + c4 * 4)
                                       : make_float4(0.f, 0.f, 0.f, 0.f);
                } else {
                    rg[it] = *(const float4*)(Bm + (size_t)(n0 + row - BM) * ldb + kt + c4 * 4);
                }
            }
        }

        // compute on smem stage ch&1
        {
            const uint32_t sbase = sb0 + (ch & 1) * STAGE_B;
#pragma unroll
            for (int ks = 0; ks < 2; ks++) {
                uint32_t ah[4][4], al[4][4], bh[4][2], bl[4][2];
                int arow = warp_m * 64 + (lane & 15);
                int acol = ks * 16 + (lane >> 4) * 8;
#pragma unroll
                for (int mt = 0; mt < 4; mt++) {
                    uint32_t ad = sbase + ((arow + mt * 16) * LDA + acol) * 2;
                    ldsm4(ah[mt], ad);
                    ldsm4(al[mt], ad + TILE_H);
                }
                int brow = warp_n * 32 + (lane & 7);
                int bcol = ks * 16 + ((lane >> 3) & 1) * 8;
#pragma unroll
                for (int nt = 0; nt < 4; nt++) {
                    uint32_t bd = sbase + 2 * TILE_H + ((brow + nt * 8) * LDA + bcol) * 2;
                    ldsm2(bh[nt], bd);
                    ldsm2(bl[nt], bd + TILE_H);
                }
                // 3 passes, accumulator touched once per pass -> no RAW stalls
#pragma unroll
                for (int mt = 0; mt < 4; mt++)
#pragma unroll
                    for (int nt = 0; nt < 4; nt++) mma16816(c[mt][nt], ah[mt], bh[nt]);
#pragma unroll
                for (int mt = 0; mt < 4; mt++)
#pragma unroll
                    for (int nt = 0; nt < 4; nt++) mma16816(c[mt][nt], ah[mt], bl[nt]);
#pragma unroll
                for (int mt = 0; mt < 4; mt++)
#pragma unroll
                    for (int nt = 0; nt < 4; nt++) mma16816(c[mt][nt], al[mt], bh[nt]);
            }
        }

        // convert + store next chunk into other stage
        if (ch + 1 < nch) {
            char* base = dyn + ((ch + 1) & 1) * STAGE_B;
#pragma unroll
            for (int it = 0; it < 8; it++) {
                int id = tid + it * 256;
                int row = (it < 4) ? (id >> 3) : ((id >> 3) - BM);
                int c4 = id & 7;
                float4 v = rg[it];
                half hx = __float2half_rn(v.x), hy = __float2half_rn(v.y);
                half hz = __float2half_rn(v.z), hw = __float2half_rn(v.w);
                half lx = __float2half_rn(v.x - __half2float(hx));
                half ly = __float2half_rn(v.y - __half2float(hy));
                half lz = __float2half_rn(v.z - __half2float(hz));
                half lw = __float2half_rn(v.w - __half2float(hw));
                char* h = base + ((it < 4) ? 0 : 2 * TILE_H) + (row * LDA + c4 * 4) * 2;
                *(uint2*)h = make_uint2(packh(hx, hy), packh(hz, hw));
                *(uint2*)(h + TILE_H) = make_uint2(packh(lx, ly), packh(lz, lw));
            }
        }
        __syncthreads();
    }

    // ---------------- epilogue ----------------
    const int cbase = n0 + warp_n * 32 + (lane & 3) * 2;
#pragma unroll
    for (int mt = 0; mt < 4; mt++) {
#pragma unroll
        for (int half_i = 0; half_i < 2; half_i++) {
            int r = warp_m * 64 + mt * 16 + (lane >> 2) + half_i * 8;
            int t = s_row[r];
            if (t < 0) continue;
            float wgt = (MODE == DOWN_R) ? s_wt[r] : 0.f;
            float* dst;
            if (MODE == DOWN_S)      dst = &g_hs[t][0];
            else if (MODE == DOWN_R) dst = &g_h[kidx][t][0];
            else                     dst = out + (size_t)t * DD;
            int sel0 = 0, sel1 = 0; float w0 = 0.f, w1 = 0.f;
            if (MODE == UP_S) {
                sel0 = g_sel[t][0]; sel1 = g_sel[t][1];
                w0 = g_wgt[t][0];   w1 = g_wgt[t][1];
            }
#pragma unroll
            for (int nt = 0; nt < 4; nt++) {
                int n = cbase + nt * 8;
                float v0 = c[mt][nt][half_i * 2 + 0];
                float v1 = c[mt][nt][half_i * 2 + 1];
                float2 o;
                if (MODE == DOWN_S) {
                    o.x = gelu_f(v0 + bias[n]);
                    o.y = gelu_f(v1 + bias[n + 1]);
                } else if (MODE == DOWN_R) {
                    const float* bp = bias + (size_t)eidx * BB + n;
                    o.x = gelu_f(v0 + bp[0]) * wgt;
                    o.y = gelu_f(v1 + bp[1]) * wgt;
                } else if (MODE == UP_S) {
                    const float* b0p = bu + (size_t)sel0 * DD + n;
                    const float* b1p = bu + (size_t)sel1 * DD + n;
                    o.x = v0 + bias[n]     + w0 * b0p[0] + w1 * b1p[0];
                    o.y = v1 + bias[n + 1] + w0 * b0p[1] + w1 * b1p[1];
                } else { // UP_R: race-free += (one slot per token per launch)
                    float2 old = *(float2*)(dst + n);
                    o.x = old.x + v0;
                    o.y = old.y + v1;
                }
                *(float2*)(dst + n) = o;
            }
        }
    }
}

extern "C" void kernel_launch(void* const* d_in, const int* in_sizes, int n_in,
                              void* d_out, int out_size) {
    const float* x   = (const float*)d_in[0];
    const float* gw  = (const float*)d_in[1];
    const float* wd  = (const float*)d_in[2];
    const float* bd  = (const float*)d_in[3];
    const float* wu  = (const float*)d_in[4];
    const float* bu  = (const float*)d_in[5];
    const float* wsd = (const float*)d_in[6];
    const float* bsd = (const float*)d_in[7];
    const float* wsu = (const float*)d_in[8];
    const float* bsu = (const float*)d_in[9];
    float* out = (float*)d_out;

    cudaFuncSetAttribute(k_mma<DOWN_S>, cudaFuncAttributeMaxDynamicSharedMemorySize, DSMEM);
    cudaFuncSetAttribute(k_mma<DOWN_R>, cudaFuncAttributeMaxDynamicSharedMemorySize, DSMEM);
    cudaFuncSetAttribute(k_mma<UP_S>,   cudaFuncAttributeMaxDynamicSharedMemorySize, DSMEM);
    cudaFuncSetAttribute(k_mma<UP_R>,   cudaFuncAttributeMaxDynamicSharedMemorySize, DSMEM);

    k_reset<<<1, 32>>>();
    k_route<<<TT / 8, 256>>>(x, gw);

    k_mma<DOWN_S><<<dim3(TT / BM, BB / BN), 256, DSMEM>>>(x, wsd, bsd, nullptr, nullptr, 0);
    k_mma<DOWN_R><<<dim3(TT / BM, BB / BN, NBK), 256, DSMEM>>>(x, wd, bd, nullptr, nullptr, 0);
    k_mma<UP_S><<<dim3(TT / BM, DD / BN), 256, DSMEM>>>(x, wsu, bsu, bu, out, 0);
    k_mma<UP_R><<<dim3(TT / BM, DD / BN, NE), 256, DSMEM>>>(x, wu, nullptr, nullptr, out, 0);
    k_mma<UP_R><<<dim3(TT / BM, DD / BN, NE), 256, DSMEM>>>(x, wu, nullptr, nullptr, out, 1);
}

// round 5
// speedup vs baseline: 2.3615x; 1.1251x over previous
#include <cuda_runtime.h>
#include <cuda_fp16.h>
#include <math.h>
#include <stdint.h>

#define TT   8192
#define DD   2048
#define NE   8
#define BB   512
#define NBK  16

#define BM   128
#define BN   128
#define BK   32
#define LDA  40                     // halves per smem row (64B data + 16B pad)
#define TILE_H  (BM * LDA * 2)      // 10240 B per plane
#define STAGE_B (4 * TILE_H)        // 40960 B (Ah, Al, Bh, Bl)
#define DSMEM   (2 * STAGE_B)       // 81920 B

// ---------------- scratch (static device globals) ----------------
__device__ int    g_cnt[NBK];
__device__ int    g_tok[NBK][TT];
__device__ float  g_twt[NBK][TT];
__device__ int    g_sel[TT][2];
__device__ float  g_wgt[TT][2];
// fp16 hi/lo planes: [plane][...]
__device__ __half xs[2][TT][DD];
__device__ __half wdp[2][NE][BB][DD];
__device__ __half wup[2][NE][DD][BB];
__device__ __half wsdp[2][BB][DD];
__device__ __half wsup[2][DD][BB];
__device__ __half ghp[2][2][TT][BB];    // [plane][k]
__device__ __half ghsp[2][TT][BB];

__device__ __forceinline__ uint32_t smem_u32(const void* p) {
    uint32_t a;
    asm("{ .reg .u64 t; cvta.to.shared.u64 t, %1; cvt.u32.u64 %0, t; }" : "=r"(a) : "l"(p));
    return a;
}
__device__ __forceinline__ void ldsm4(uint32_t* r, uint32_t a) {
    asm volatile("ldmatrix.sync.aligned.m8n8.x4.shared.b16 {%0,%1,%2,%3}, [%4];"
                 : "=r"(r[0]), "=r"(r[1]), "=r"(r[2]), "=r"(r[3]) : "r"(a));
}
__device__ __forceinline__ void ldsm2(uint32_t* r, uint32_t a) {
    asm volatile("ldmatrix.sync.aligned.m8n8.x2.shared.b16 {%0,%1}, [%2];"
                 : "=r"(r[0]), "=r"(r[1]) : "r"(a));
}
__device__ __forceinline__ void mma16816(float* c, const uint32_t* a, const uint32_t* b) {
    asm volatile("mma.sync.aligned.m16n8k16.row.col.f32.f16.f16.f32 "
                 "{%0,%1,%2,%3}, {%4,%5,%6,%7}, {%8,%9}, {%0,%1,%2,%3};"
                 : "+f"(c[0]), "+f"(c[1]), "+f"(c[2]), "+f"(c[3])
                 : "r"(a[0]), "r"(a[1]), "r"(a[2]), "r"(a[3]), "r"(b[0]), "r"(b[1]));
}
#define CPA16(dst, src, sz) \
    asm volatile("cp.async.cg.shared.global [%0], [%1], 16, %2;" \
                 :: "r"(dst), "l"(src), "r"(sz) : "memory")
#define CPC()  asm volatile("cp.async.commit_group;" ::: "memory")
#define CPW(n) asm volatile("cp.async.wait_group %0;" :: "n"(n) : "memory")

__device__ __forceinline__ uint32_t packh(half a, half b) {
    __half2 h = __halves2half2(a, b);
    return *(uint32_t*)&h;
}
__device__ __forceinline__ void split2(float a, float b, uint32_t& hi, uint32_t& lo) {
    half ha = __float2half_rn(a), hb = __float2half_rn(b);
    half la = __float2half_rn(a - __half2float(ha));
    half lb = __float2half_rn(b - __half2float(hb));
    hi = packh(ha, hb); lo = packh(la, lb);
}
__device__ __forceinline__ float gelu_f(float v) {
    return 0.5f * v * (1.0f + erff(v * 0.70710678118654752f));
}

// ---------------- setup kernels ----------------
__global__ void k_reset() {
    if (threadIdx.x < NBK) g_cnt[threadIdx.x] = 0;
}

// fp32 -> fp16 hi/lo split (lo plane at d + n)
__global__ void k_cvt(const float* __restrict__ s, __half* __restrict__ d, int n) {
    int stride = gridDim.x * blockDim.x;
    for (int i = blockIdx.x * blockDim.x + threadIdx.x; i < n / 4; i += stride) {
        float4 v = ((const float4*)s)[i];
        uint32_t h0, l0, h1, l1;
        split2(v.x, v.y, h0, l0);
        split2(v.z, v.w, h1, l1);
        *(uint2*)(d + i * 4)     = make_uint2(h0, h1);
        *(uint2*)(d + n + i * 4) = make_uint2(l0, l1);
    }
}

// routing + x conversion (one warp per token)
__global__ void k_route(const float* __restrict__ x, const float* __restrict__ gw) {
    int t    = blockIdx.x * 8 + (threadIdx.x >> 5);
    int lane = threadIdx.x & 31;
    if (t >= TT) return;
    const float4* xr = (const float4*)(x + (size_t)t * DD);
    float acc[NE];
#pragma unroll
    for (int e = 0; e < NE; e++) acc[e] = 0.f;
    for (int i = lane; i < DD / 4; i += 32) {
        float4 xv = xr[i];
        uint32_t h0, l0, h1, l1;
        split2(xv.x, xv.y, h0, l0);
        split2(xv.z, xv.w, h1, l1);
        *(uint2*)(&xs[0][t][i * 4]) = make_uint2(h0, h1);
        *(uint2*)(&xs[1][t][i * 4]) = make_uint2(l0, l1);
#pragma unroll
        for (int e = 0; e < NE; e++) {
            float4 gv = ((const float4*)(gw + (size_t)e * DD))[i];
            acc[e] += xv.x * gv.x + xv.y * gv.y + xv.z * gv.z + xv.w * gv.w;
        }
    }
#pragma unroll
    for (int e = 0; e < NE; e++)
#pragma unroll
        for (int o = 16; o > 0; o >>= 1)
            acc[e] += __shfl_down_sync(0xffffffffu, acc[e], o);
    if (lane == 0) {
        float mx = acc[0];
#pragma unroll
        for (int e = 1; e < NE; e++) mx = fmaxf(mx, acc[e]);
        float p[NE];
#pragma unroll
        for (int e = 0; e < NE; e++) p[e] = expf(acc[e] - mx);
        int i1 = 0;
#pragma unroll
        for (int e = 1; e < NE; e++) if (p[e] > p[i1]) i1 = e;
        int i2 = (i1 == 0) ? 1 : 0;
#pragma unroll
        for (int e = 0; e < NE; e++) { if (e != i1 && p[e] > p[i2]) i2 = e; }
        float w1 = p[i1], w2 = p[i2];
        float inv = 1.0f / (w1 + w2);
        w1 *= inv; w2 *= inv;
        g_sel[t][0] = i1; g_sel[t][1] = i2;
        g_wgt[t][0] = w1; g_wgt[t][1] = w2;
        int b0 = i1 * 2;
        int s0 = atomicAdd(&g_cnt[b0], 1);
        g_tok[b0][s0] = t; g_twt[b0][s0] = w1;
        int b1 = i2 * 2 + 1;
        int s1 = atomicAdd(&g_cnt[b1], 1);
        g_tok[b1][s1] = t; g_twt[b1][s1] = w2;
    }
}

// ---------------- mma.sync 3xFP16 GEMM, cp.async pipelined ----------------
enum { DOWN_S = 0, DOWN_R = 1, UP_S = 2, UP_R = 3 };

template <int MODE>
__global__ __launch_bounds__(256, 2) void k_mma(
    const float* __restrict__ bias, const float* __restrict__ bu,
    float* __restrict__ out, int kk)
{
    extern __shared__ char dyn[];
    __shared__ int   s_row[BM];
    __shared__ float s_wt[BM];

    const int tid = threadIdx.x, wid = tid >> 5, lane = tid & 31;
    const int m0 = blockIdx.x * BM, n0 = blockIdx.y * BN;

    int M = TT, eidx = 0, kidx = 0;
    const int* tok = nullptr;
    const float* twt = nullptr;
    if (MODE == DOWN_R || MODE == UP_R) {
        int bucket = (MODE == DOWN_R) ? (int)blockIdx.z : ((int)blockIdx.z * 2 + kk);
        M = g_cnt[bucket];
        if (m0 >= M) return;
        eidx = bucket >> 1;
        kidx = bucket & 1;
        tok = g_tok[bucket];
        twt = g_twt[bucket];
    }

    const __half* Ah; size_t dA; int lda;
    const __half* Bh; size_t dB; int ldb; int Kd;
    if (MODE == DOWN_S)      { Ah = &xs[0][0][0];         dA = (size_t)TT * DD;      lda = DD;
                               Bh = &wsdp[0][0][0];       dB = (size_t)BB * DD;      ldb = DD; Kd = DD; }
    else if (MODE == DOWN_R) { Ah = &xs[0][0][0];         dA = (size_t)TT * DD;      lda = DD;
                               Bh = &wdp[0][eidx][0][0];  dB = (size_t)NE * BB * DD; ldb = DD; Kd = DD; }
    else if (MODE == UP_S)   { Ah = &ghsp[0][0][0];       dA = (size_t)TT * BB;      lda = BB;
                               Bh = &wsup[0][0][0];       dB = (size_t)DD * BB;      ldb = BB; Kd = BB; }
    else                     { Ah = &ghp[0][kk][0][0];    dA = (size_t)2 * TT * BB;  lda = BB;
                               Bh = &wup[0][eidx][0][0];  dB = (size_t)NE * DD * BB; ldb = BB; Kd = BB; }

    if (tid < BM) {
        int r = m0 + tid;
        if (MODE == DOWN_R || MODE == UP_R) {
            s_row[tid] = (r < M) ? tok[r] : -1;
            s_wt[tid]  = (r < M) ? twt[r] : 0.f;
        } else {
            s_row[tid] = r;
        }
    }
    __syncthreads();

    // per-thread cp.async slots: rows rowA & rowA+64, 16B chunk c16, 4 planes
    const int rowA = tid >> 2, c16 = tid & 3;
    uint32_t szA0 = 16, szA1 = 16;
    int sr0 = s_row[rowA], sr1 = s_row[rowA + 64];
    if (MODE == DOWN_R || MODE == UP_R) {
        if (sr0 < 0) { sr0 = 0; szA0 = 0; }
        if (sr1 < 0) { sr1 = 0; szA1 = 0; }
    }
    const char* pA0 = (const char*)(Ah + (size_t)sr0 * lda) + c16 * 16;
    const char* pA1 = (const char*)(Ah + (size_t)sr1 * lda) + c16 * 16;
    const char* pB0 = (const char*)(Bh + (size_t)(n0 + rowA) * ldb) + c16 * 16;
    const char* pB1 = (const char*)(Bh + (size_t)(n0 + rowA + 64) * ldb) + c16 * 16;
    const size_t dAb = dA * 2, dBb = dB * 2;

    const uint32_t sb0 = smem_u32(dyn);
    const uint32_t sd0 = sb0 + (rowA * LDA + c16 * 8) * 2;
    const uint32_t sd1 = sd0 + 64 * LDA * 2;

    auto issue = [&](int stage) {
        uint32_t st = stage ? STAGE_B : 0u;
        CPA16(sd0 + st,              pA0,       szA0);
        CPA16(sd0 + st + TILE_H,     pA0 + dAb, szA0);
        CPA16(sd1 + st,              pA1,       szA1);
        CPA16(sd1 + st + TILE_H,     pA1 + dAb, szA1);
        CPA16(sd0 + st + 2*TILE_H,   pB0,       16u);
        CPA16(sd0 + st + 3*TILE_H,   pB0 + dBb, 16u);
        CPA16(sd1 + st + 2*TILE_H,   pB1,       16u);
        CPA16(sd1 + st + 3*TILE_H,   pB1 + dBb, 16u);
        CPC();
        pA0 += 64; pA1 += 64; pB0 += 64; pB1 += 64;
    };

    const int warp_m = wid >> 2, warp_n = wid & 3;   // 2 x 4 warps, 64x32 tile
    float c[4][4][4];
#pragma unroll
    for (int i = 0; i < 4; i++)
#pragma unroll
        for (int j = 0; j < 4; j++)
#pragma unroll
            for (int q = 0; q < 4; q++) c[i][j][q] = 0.f;

    const int nch = Kd / BK;
    issue(0);

    for (int ch = 0; ch < nch; ch++) {
        if (ch + 1 < nch) { issue((ch + 1) & 1); CPW(1); }
        else              { CPW(0); }
        __syncthreads();

        const uint32_t sbase = sb0 + (ch & 1) * STAGE_B;
#pragma unroll
        for (int ks = 0; ks < 2; ks++) {
            uint32_t ah[4][4], al[4][4], bh[4][2], bl[4][2];
            int arow = warp_m * 64 + (lane & 15);
            int acol = ks * 16 + (lane >> 4) * 8;
#pragma unroll
            for (int mt = 0; mt < 4; mt++) {
                uint32_t ad = sbase + ((arow + mt * 16) * LDA + acol) * 2;
                ldsm4(ah[mt], ad);
                ldsm4(al[mt], ad + TILE_H);
            }
            int brow = warp_n * 32 + (lane & 7);
            int bcol = ks * 16 + ((lane >> 3) & 1) * 8;
#pragma unroll
            for (int nt = 0; nt < 4; nt++) {
                uint32_t bd = sbase + 2 * TILE_H + ((brow + nt * 8) * LDA + bcol) * 2;
                ldsm2(bh[nt], bd);
                ldsm2(bl[nt], bd + TILE_H);
            }
#pragma unroll
            for (int mt = 0; mt < 4; mt++)
#pragma unroll
                for (int nt = 0; nt < 4; nt++) mma16816(c[mt][nt], ah[mt], bh[nt]);
#pragma unroll
            for (int mt = 0; mt < 4; mt++)
#pragma unroll
                for (int nt = 0; nt < 4; nt++) mma16816(c[mt][nt], ah[mt], bl[nt]);
#pragma unroll
            for (int mt = 0; mt < 4; mt++)
#pragma unroll
                for (int nt = 0; nt < 4; nt++) mma16816(c[mt][nt], al[mt], bh[nt]);
        }
        __syncthreads();
    }

    // ---------------- epilogue ----------------
    const int cbase = n0 + warp_n * 32 + (lane & 3) * 2;
#pragma unroll
    for (int mt = 0; mt < 4; mt++) {
#pragma unroll
        for (int half_i = 0; half_i < 2; half_i++) {
            int r = warp_m * 64 + mt * 16 + (lane >> 2) + half_i * 8;
            int t = s_row[r];
            if (t < 0) continue;
            float wgt = (MODE == DOWN_R) ? s_wt[r] : 0.f;
            int sel0 = 0, sel1 = 0; float w0 = 0.f, w1 = 0.f;
            if (MODE == UP_S) {
                sel0 = g_sel[t][0]; sel1 = g_sel[t][1];
                w0 = g_wgt[t][0];   w1 = g_wgt[t][1];
            }
#pragma unroll
            for (int nt = 0; nt < 4; nt++) {
                int n = cbase + nt * 8;
                float v0 = c[mt][nt][half_i * 2 + 0];
                float v1 = c[mt][nt][half_i * 2 + 1];
                if (MODE == DOWN_S) {
                    float o0 = gelu_f(v0 + bias[n]);
                    float o1 = gelu_f(v1 + bias[n + 1]);
                    uint32_t hi, lo;
                    split2(o0, o1, hi, lo);
                    *(uint32_t*)&ghsp[0][t][n] = hi;
                    *(uint32_t*)&ghsp[1][t][n] = lo;
                } else if (MODE == DOWN_R) {
                    const float* bp = bias + (size_t)eidx * BB + n;
                    float o0 = gelu_f(v0 + bp[0]) * wgt;
                    float o1 = gelu_f(v1 + bp[1]) * wgt;
                    uint32_t hi, lo;
                    split2(o0, o1, hi, lo);
                    *(uint32_t*)&ghp[0][kidx][t][n] = hi;
                    *(uint32_t*)&ghp[1][kidx][t][n] = lo;
                } else if (MODE == UP_S) {
                    const float* b0p = bu + (size_t)sel0 * DD + n;
                    const float* b1p = bu + (size_t)sel1 * DD + n;
                    float2 o;
                    o.x = v0 + bias[n]     + w0 * b0p[0] + w1 * b1p[0];
                    o.y = v1 + bias[n + 1] + w0 * b0p[1] + w1 * b1p[1];
                    *(float2*)(out + (size_t)t * DD + n) = o;
                } else { // UP_R: race-free += (one slot per token per launch)
                    float* dp = out + (size_t)t * DD + n;
                    float2 old = *(float2*)dp;
                    old.x += v0; old.y += v1;
                    *(float2*)dp = old;
                }
            }
        }
    }
}

extern "C" void kernel_launch(void* const* d_in, const int* in_sizes, int n_in,
                              void* d_out, int out_size) {
    const float* x   = (const float*)d_in[0];
    const float* gw  = (const float*)d_in[1];
    const float* wd  = (const float*)d_in[2];
    const float* bd  = (const float*)d_in[3];
    const float* wu  = (const float*)d_in[4];
    const float* bu  = (const float*)d_in[5];
    const float* wsd = (const float*)d_in[6];
    const float* bsd = (const float*)d_in[7];
    const float* wsu = (const float*)d_in[8];
    const float* bsu = (const float*)d_in[9];
    float* out = (float*)d_out;

    static __half* wdp_p = nullptr;
    cudaFuncSetAttribute(k_mma<DOWN_S>, cudaFuncAttributeMaxDynamicSharedMemorySize, DSMEM);
    cudaFuncSetAttribute(k_mma<DOWN_R>, cudaFuncAttributeMaxDynamicSharedMemorySize, DSMEM);
    cudaFuncSetAttribute(k_mma<UP_S>,   cudaFuncAttributeMaxDynamicSharedMemorySize, DSMEM);
    cudaFuncSetAttribute(k_mma<UP_R>,   cudaFuncAttributeMaxDynamicSharedMemorySize, DSMEM);
    (void)wdp_p;

    // device-symbol addresses for conversion targets
    __half *p_wd, *p_wu, *p_wsd, *p_wsu;
    cudaGetSymbolAddress((void**)&p_wd,  wdp);
    cudaGetSymbolAddress((void**)&p_wu,  wup);
    cudaGetSymbolAddress((void**)&p_wsd, wsdp);
    cudaGetSymbolAddress((void**)&p_wsu, wsup);

    k_reset<<<1, 32>>>();
    k_cvt<<<4096, 256>>>(wd,  p_wd,  NE * BB * DD);
    k_cvt<<<4096, 256>>>(wu,  p_wu,  NE * DD * BB);
    k_cvt<<<1024, 256>>>(wsd, p_wsd, BB * DD);
    k_cvt<<<1024, 256>>>(wsu, p_wsu, DD * BB);
    k_route<<<TT / 8, 256>>>(x, gw);

    k_mma<DOWN_S><<<dim3(TT / BM, BB / BN), 256, DSMEM>>>(bsd, nullptr, nullptr, 0);
    k_mma<DOWN_R><<<dim3(TT / BM, BB / BN, NBK), 256, DSMEM>>>(bd, nullptr, nullptr, 0);
    k_mma<UP_S><<<dim3(TT / BM, DD / BN), 256, DSMEM>>>(bsu, bu, out, 0);
    k_mma<UP_R><<<dim3(TT / BM, DD / BN, NE), 256, DSMEM>>>(nullptr, nullptr, out, 0);
    k_mma<UP_R><<<dim3(TT / BM, DD / BN, NE), 256, DSMEM>>>(nullptr, nullptr, out, 1);
}

// round 6
// speedup vs baseline: 5.3373x; 2.2601x over previous
#include <cuda_runtime.h>
#include <cuda_fp16.h>
#include <math.h>
#include <stdint.h>

#define TT   8192
#define DD   2048
#define NE   8
#define BB   512
#define NBK  16

#define BM   128
#define BN   128
#define BK   64
#define LDA  72                      // halves per smem row (128B data + 16B pad)
#define STAGE_B (256 * LDA * 2)      // 36864 B (128 A rows + 128 B rows)
#define DSMEM   (2 * STAGE_B)        // 73728 B

// ---------------- scratch (static device globals) ----------------
__device__ int    g_cnt[NBK];
__device__ int    g_tok[NBK][TT];
__device__ float  g_twt[NBK][TT];
__device__ int    g_sel[TT][2];
__device__ float  g_wgt[TT][2];
__device__ __align__(16) __half xs[TT][DD];
__device__ __align__(16) __half wdp[NE][BB][DD];
__device__ __align__(16) __half wup[NE][DD][BB];
__device__ __align__(16) __half wsdp[BB][DD];
__device__ __align__(16) __half wsup[DD][BB];
__device__ __align__(16) __half ghp[2][TT][BB];
__device__ __align__(16) __half ghsp[TT][BB];

__device__ __forceinline__ uint32_t smem_u32(const void* p) {
    uint32_t a;
    asm("{ .reg .u64 t; cvta.to.shared.u64 t, %1; cvt.u32.u64 %0, t; }" : "=r"(a) : "l"(p));
    return a;
}
__device__ __forceinline__ void ldsm4(uint32_t* r, uint32_t a) {
    asm volatile("ldmatrix.sync.aligned.m8n8.x4.shared.b16 {%0,%1,%2,%3}, [%4];"
                 : "=r"(r[0]), "=r"(r[1]), "=r"(r[2]), "=r"(r[3]) : "r"(a));
}
__device__ __forceinline__ void mma16816(float* c, const uint32_t* a, const uint32_t* b) {
    asm volatile("mma.sync.aligned.m16n8k16.row.col.f32.f16.f16.f32 "
                 "{%0,%1,%2,%3}, {%4,%5,%6,%7}, {%8,%9}, {%0,%1,%2,%3};"
                 : "+f"(c[0]), "+f"(c[1]), "+f"(c[2]), "+f"(c[3])
                 : "r"(a[0]), "r"(a[1]), "r"(a[2]), "r"(a[3]), "r"(b[0]), "r"(b[1]));
}
#define CPA16(dst, src, sz) \
    asm volatile("cp.async.cg.shared.global [%0], [%1], 16, %2;" \
                 :: "r"(dst), "l"(src), "r"(sz) : "memory")
#define CPC()  asm volatile("cp.async.commit_group;" ::: "memory")
#define CPW(n) asm volatile("cp.async.wait_group %0;" :: "n"(n) : "memory")

__device__ __forceinline__ uint32_t packh(half a, half b) {
    __half2 h = __halves2half2(a, b);
    return *(uint32_t*)&h;
}
__device__ __forceinline__ float gelu_f(float v) {
    return 0.5f * v * (1.0f + erff(v * 0.70710678118654752f));
}

// ---------------- setup kernels ----------------
__global__ void k_reset() {
    if (threadIdx.x < NBK) g_cnt[threadIdx.x] = 0;
}

// fp32 -> fp16 (plain), 8 elems/thread
__global__ void k_cvt(const float* __restrict__ s, __half* __restrict__ d, int n) {
    int stride = gridDim.x * blockDim.x;
    for (int i = blockIdx.x * blockDim.x + threadIdx.x; i < n / 8; i += stride) {
        float4 v0 = ((const float4*)s)[2 * i];
        float4 v1 = ((const float4*)s)[2 * i + 1];
        uint4 o;
        o.x = packh(__float2half_rn(v0.x), __float2half_rn(v0.y));
        o.y = packh(__float2half_rn(v0.z), __float2half_rn(v0.w));
        o.z = packh(__float2half_rn(v1.x), __float2half_rn(v1.y));
        o.w = packh(__float2half_rn(v1.z), __float2half_rn(v1.w));
        *(uint4*)(d + i * 8) = o;
    }
}

// routing (fp32 logits) + x fp16 conversion; one warp per token
__global__ void k_route(const float* __restrict__ x, const float* __restrict__ gw) {
    int t    = blockIdx.x * 8 + (threadIdx.x >> 5);
    int lane = threadIdx.x & 31;
    if (t >= TT) return;
    const float4* xr = (const float4*)(x + (size_t)t * DD);
    float acc[NE];
#pragma unroll
    for (int e = 0; e < NE; e++) acc[e] = 0.f;
    for (int i = lane; i < DD / 4; i += 32) {
        float4 xv = xr[i];
        *(uint2*)(&xs[t][i * 4]) = make_uint2(
            packh(__float2half_rn(xv.x), __float2half_rn(xv.y)),
            packh(__float2half_rn(xv.z), __float2half_rn(xv.w)));
#pragma unroll
        for (int e = 0; e < NE; e++) {
            float4 gv = ((const float4*)(gw + (size_t)e * DD))[i];
            acc[e] += xv.x * gv.x + xv.y * gv.y + xv.z * gv.z + xv.w * gv.w;
        }
    }
#pragma unroll
    for (int e = 0; e < NE; e++)
#pragma unroll
        for (int o = 16; o > 0; o >>= 1)
            acc[e] += __shfl_down_sync(0xffffffffu, acc[e], o);
    if (lane == 0) {
        float mx = acc[0];
#pragma unroll
        for (int e = 1; e < NE; e++) mx = fmaxf(mx, acc[e]);
        float p[NE];
#pragma unroll
        for (int e = 0; e < NE; e++) p[e] = expf(acc[e] - mx);
        int i1 = 0;
#pragma unroll
        for (int e = 1; e < NE; e++) if (p[e] > p[i1]) i1 = e;
        int i2 = (i1 == 0) ? 1 : 0;
#pragma unroll
        for (int e = 0; e < NE; e++) { if (e != i1 && p[e] > p[i2]) i2 = e; }
        float w1 = p[i1], w2 = p[i2];
        float inv = 1.0f / (w1 + w2);
        w1 *= inv; w2 *= inv;
        g_sel[t][0] = i1; g_sel[t][1] = i2;
        g_wgt[t][0] = w1; g_wgt[t][1] = w2;
        int b0 = i1 * 2;
        int s0 = atomicAdd(&g_cnt[b0], 1);
        g_tok[b0][s0] = t; g_twt[b0][s0] = w1;
        int b1 = i2 * 2 + 1;
        int s1 = atomicAdd(&g_cnt[b1], 1);
        g_tok[b1][s1] = t; g_twt[b1][s1] = w2;
    }
}

// ---------------- single-pass fp16 mma GEMM, cp.async double-buffered ----------------
enum { DOWN_S = 0, DOWN_R = 1, UP_S = 2, UP_R = 3 };

template <int MODE>
__global__ __launch_bounds__(256, 2) void k_mma(
    const float* __restrict__ bias, const float* __restrict__ bu,
    float* __restrict__ out, int kk)
{
    extern __shared__ char dyn[];
    __shared__ int   s_row[BM];
    __shared__ float s_wt[BM];

    const int tid = threadIdx.x, wid = tid >> 5, lane = tid & 31;
    const int m0 = blockIdx.x * BM, n0 = blockIdx.y * BN;

    int M = TT, eidx = 0, kidx = 0;
    const int* tok = nullptr;
    const float* twt = nullptr;
    if (MODE == DOWN_R || MODE == UP_R) {
        int bucket = (MODE == DOWN_R) ? (int)blockIdx.z : ((int)blockIdx.z * 2 + kk);
        M = g_cnt[bucket];
        if (m0 >= M) return;
        eidx = bucket >> 1;
        kidx = bucket & 1;
        tok = g_tok[bucket];
        twt = g_twt[bucket];
    }

    const __half* Ah; int lda;
    const __half* Bh; int ldb; int Kd;
    if (MODE == DOWN_S)      { Ah = &xs[0][0];        lda = DD; Bh = &wsdp[0][0];       ldb = DD; Kd = DD; }
    else if (MODE == DOWN_R) { Ah = &xs[0][0];        lda = DD; Bh = &wdp[eidx][0][0];  ldb = DD; Kd = DD; }
    else if (MODE == UP_S)   { Ah = &ghsp[0][0];      lda = BB; Bh = &wsup[0][0];       ldb = BB; Kd = BB; }
    else                     { Ah = &ghp[kk][0][0];   lda = BB; Bh = &wup[eidx][0][0];  ldb = BB; Kd = BB; }

    if (tid < BM) {
        int r = m0 + tid;
        if (MODE == DOWN_R || MODE == UP_R) {
            s_row[tid] = (r < M) ? tok[r] : -1;
            s_wt[tid]  = (r < M) ? twt[r] : 0.f;
        } else {
            s_row[tid] = r;
        }
    }
    __syncthreads();

    // cp.async: thread -> rows {lrow + 32*j}, 16B chunk lch (BK=64 -> 128B/row)
    const int lrow = tid >> 3, lch = tid & 7;
    const char* pA[4];
    uint32_t amask = 0;
#pragma unroll
    for (int j = 0; j < 4; j++) {
        int r = lrow + 32 * j;               // A row 0..127
        int sr = s_row[r];
        uint32_t ok = 1;
        if (MODE == DOWN_R || MODE == UP_R) {
            if (sr < 0) { sr = 0; ok = 0; }
        }
        amask |= ok << j;
        pA[j] = (const char*)(Ah + (size_t)sr * lda) + lch * 16;
    }
    const char* pB = (const char*)(Bh + (size_t)(n0 + lrow) * ldb) + lch * 16;
    const size_t bstride = (size_t)32 * ldb * 2;

    const uint32_t sb0 = smem_u32(dyn);
    const uint32_t sp0 = sb0 + (lrow * LDA + lch * 8) * 2;
    const uint32_t rowstep = 32 * LDA * 2;

    auto issue = [&](int stage) {
        uint32_t st = stage ? (uint32_t)STAGE_B : 0u;
#pragma unroll
        for (int j = 0; j < 4; j++)
            CPA16(sp0 + st + j * rowstep, pA[j], ((amask >> j) & 1) * 16);
#pragma unroll
        for (int j = 0; j < 4; j++)
            CPA16(sp0 + st + (j + 4) * rowstep, pB + j * bstride, 16);
        CPC();
#pragma unroll
        for (int j = 0; j < 4; j++) pA[j] += 128;
        pB += 128;
    };

    const int warp_m = wid >> 2, warp_n = wid & 3;   // 2 x 4 warps, 64x32 each
    float c[4][4][4];
#pragma unroll
    for (int i = 0; i < 4; i++)
#pragma unroll
        for (int j = 0; j < 4; j++)
#pragma unroll
            for (int q = 0; q < 4; q++) c[i][j][q] = 0.f;

    const int nch = Kd / BK;
    issue(0);

    for (int ch = 0; ch < nch; ch++) {
        if (ch + 1 < nch) { issue((ch + 1) & 1); CPW(1); }
        else              { CPW(0); }
        __syncthreads();

        const uint32_t sbase = sb0 + (ch & 1) * STAGE_B;
#pragma unroll
        for (int ks = 0; ks < 4; ks++) {
            uint32_t a[4][4], b[4][2];
            int arow = warp_m * 64 + (lane & 15);
            int acol = ks * 16 + (lane >> 4) * 8;
#pragma unroll
            for (int mt = 0; mt < 4; mt++)
                ldsm4(a[mt], sbase + ((arow + mt * 16) * LDA + acol) * 2);
            // B: rows 128+, ldsm4 loads two n-groups per issue
#pragma unroll
            for (int p = 0; p < 2; p++) {
                int brow = 128 + warp_n * 32 + p * 16 + ((lane >> 4) & 1) * 8 + (lane & 7);
                int bcol = ks * 16 + ((lane >> 3) & 1) * 8;
                uint32_t r4[4];
                ldsm4(r4, sbase + (brow * LDA + bcol) * 2);
                b[2 * p][0] = r4[0]; b[2 * p][1] = r4[1];
                b[2 * p + 1][0] = r4[2]; b[2 * p + 1][1] = r4[3];
            }
#pragma unroll
            for (int mt = 0; mt < 4; mt++)
#pragma unroll
                for (int nt = 0; nt < 4; nt++) mma16816(c[mt][nt], a[mt], b[nt]);
        }
        __syncthreads();
    }

    // ---------------- epilogue ----------------
    const int cbase = n0 + warp_n * 32 + (lane & 3) * 2;
#pragma unroll
    for (int mt = 0; mt < 4; mt++) {
#pragma unroll
        for (int half_i = 0; half_i < 2; half_i++) {
            int r = warp_m * 64 + mt * 16 + (lane >> 2) + half_i * 8;
            int t = s_row[r];
            if (t < 0) continue;
            float wgt = (MODE == DOWN_R) ? s_wt[r] : 0.f;
            int sel0 = 0, sel1 = 0; float w0 = 0.f, w1 = 0.f;
            if (MODE == UP_S) {
                sel0 = g_sel[t][0]; sel1 = g_sel[t][1];
                w0 = g_wgt[t][0];   w1 = g_wgt[t][1];
            }
#pragma unroll
            for (int nt = 0; nt < 4; nt++) {
                int n = cbase + nt * 8;
                float v0 = c[mt][nt][half_i * 2 + 0];
                float v1 = c[mt][nt][half_i * 2 + 1];
                if (MODE == DOWN_S) {
                    float o0 = gelu_f(v0 + bias[n]);
                    float o1 = gelu_f(v1 + bias[n + 1]);
                    *(uint32_t*)&ghsp[t][n] = packh(__float2half_rn(o0), __float2half_rn(o1));
                } else if (MODE == DOWN_R) {
                    const float* bp = bias + (size_t)eidx * BB + n;
                    float o0 = gelu_f(v0 + bp[0]) * wgt;
                    float o1 = gelu_f(v1 + bp[1]) * wgt;
                    *(uint32_t*)&ghp[kidx][t][n] = packh(__float2half_rn(o0), __float2half_rn(o1));
                } else if (MODE == UP_S) {
                    const float* b0p = bu + (size_t)sel0 * DD + n;
                    const float* b1p = bu + (size_t)sel1 * DD + n;
                    float2 o;
                    o.x = v0 + bias[n]     + w0 * b0p[0] + w1 * b1p[0];
                    o.y = v1 + bias[n + 1] + w0 * b0p[1] + w1 * b1p[1];
                    *(float2*)(out + (size_t)t * DD + n) = o;
                } else { // UP_R: race-free += (one slot per token per launch)
                    float* dp = out + (size_t)t * DD + n;
                    float2 old = *(float2*)dp;
                    old.x += v0; old.y += v1;
                    *(float2*)dp = old;
                }
            }
        }
    }
}

extern "C" void kernel_launch(void* const* d_in, const int* in_sizes, int n_in,
                              void* d_out, int out_size) {
    const float* x   = (const float*)d_in[0];
    const float* gw  = (const float*)d_in[1];
    const float* wd  = (const float*)d_in[2];
    const float* bd  = (const float*)d_in[3];
    const float* wu  = (const float*)d_in[4];
    const float* bu  = (const float*)d_in[5];
    const float* wsd = (const float*)d_in[6];
    const float* bsd = (const float*)d_in[7];
    const float* wsu = (const float*)d_in[8];
    const float* bsu = (const float*)d_in[9];
    float* out = (float*)d_out;

    cudaFuncSetAttribute(k_mma<DOWN_S>, cudaFuncAttributeMaxDynamicSharedMemorySize, DSMEM);
    cudaFuncSetAttribute(k_mma<DOWN_R>, cudaFuncAttributeMaxDynamicSharedMemorySize, DSMEM);
    cudaFuncSetAttribute(k_mma<UP_S>,   cudaFuncAttributeMaxDynamicSharedMemorySize, DSMEM);
    cudaFuncSetAttribute(k_mma<UP_R>,   cudaFuncAttributeMaxDynamicSharedMemorySize, DSMEM);

    __half *p_wd, *p_wu, *p_wsd, *p_wsu;
    cudaGetSymbolAddress((void**)&p_wd,  wdp);
    cudaGetSymbolAddress((void**)&p_wu,  wup);
    cudaGetSymbolAddress((void**)&p_wsd, wsdp);
    cudaGetSymbolAddress((void**)&p_wsu, wsup);

    k_reset<<<1, 32>>>();
    k_cvt<<<2048, 256>>>(wd,  p_wd,  NE * BB * DD);
    k_cvt<<<2048, 256>>>(wu,  p_wu,  NE * DD * BB);
    k_cvt<<<512, 256>>>(wsd, p_wsd, BB * DD);
    k_cvt<<<512, 256>>>(wsu, p_wsu, DD * BB);
    k_route<<<TT / 8, 256>>>(x, gw);

    k_mma<DOWN_S><<<dim3(TT / BM, BB / BN), 256, DSMEM>>>(bsd, nullptr, nullptr, 0);
    k_mma<DOWN_R><<<dim3(TT / BM, BB / BN, NBK), 256, DSMEM>>>(bd, nullptr, nullptr, 0);
    k_mma<UP_S><<<dim3(TT / BM, DD / BN), 256, DSMEM>>>(bsu, bu, out, 0);
    k_mma<UP_R><<<dim3(TT / BM, DD / BN, NE), 256, DSMEM>>>(nullptr, nullptr, out, 0);
    k_mma<UP_R><<<dim3(TT / BM, DD / BN, NE), 256, DSMEM>>>(nullptr, nullptr, out, 1);
}